// round 4
// baseline (speedup 1.0000x reference)
#include <cuda_runtime.h>
#include <math_constants.h>

// ROI max pooling — one block per (ROI, bin-row).
// feature_map: (4,4,16,16,512) fp32 -> viewed (16 images, 16, 16, 128 float4)
// rois: (1024, 4) fp32
// out: (1024, 7, 7, 128 float4)

#define FM_H 16
#define FM_W 16
#define PH 7
#define PW 7
#define C4 128          // 512 channels / 4
#define NROIS_PER_IMG 64

__global__ __launch_bounds__(C4) void roipool_kernel(
    const float4* __restrict__ fm,
    const float4* __restrict__ rois,   // one float4 per ROI
    float4*       __restrict__ out)
{
    const int g   = blockIdx.x;          // global ROI index
    const int bi  = blockIdx.y;          // bin row 0..6
    const int img = g / NROIS_PER_IMG;
    const int c4  = threadIdx.x;         // 0..127

    const float4 r = __ldg(&rois[g]);
    // Truncation matches jnp .astype(int32) for positive values.
    const int h0 = (int)((float)FM_H * r.x);
    const int w0 = (int)((float)FM_W * r.y);
    const int h1 = (int)((float)FM_H * r.z);
    const int w1 = (int)((float)FM_W * r.w);
    const int hs = (h1 - h0) / PH;
    const int ws = (w1 - w0) / PW;

    // Row window for this bin-row. Reference semantics: bins 0..PH-2 span hs
    // rows; last bin extends to h1. If hs<=0 all in-ROI rows fold into last bin.
    int rs, re;
    if (hs > 0) {
        rs = h0 + bi * hs;
        re = (bi == PH - 1) ? h1 : rs + hs;
    } else {
        rs = (bi == PH - 1) ? h0 : 0;
        re = (bi == PH - 1) ? h1 : 0;
    }

    // Column windows per bin-col.
    int cs[PW], ce[PW];
    #pragma unroll
    for (int bj = 0; bj < PW; ++bj) {
        if (ws > 0) {
            cs[bj] = w0 + bj * ws;
            ce[bj] = (bj == PW - 1) ? w1 : cs[bj] + ws;
        } else {
            cs[bj] = (bj == PW - 1) ? w0 : 0;
            ce[bj] = (bj == PW - 1) ? w1 : 0;
        }
    }

    const float4* base  = fm + (size_t)img * (FM_H * FM_W * C4) + c4;
    float4*       obase = out + ((size_t)g * (PH * PW) + bi * PW) * C4 + c4;

    float4 acc[PW];
    #pragma unroll
    for (int bj = 0; bj < PW; ++bj)
        acc[bj] = make_float4(-CUDART_INF_F, -CUDART_INF_F,
                              -CUDART_INF_F, -CUDART_INF_F);

    for (int h = rs; h < re; ++h) {
        const float4* row = base + (size_t)(h * FM_W) * C4;
        #pragma unroll
        for (int bj = 0; bj < PW; ++bj) {
            for (int w = cs[bj]; w < ce[bj]; ++w) {
                float4 v = __ldg(row + (size_t)w * C4);
                acc[bj].x = fmaxf(acc[bj].x, v.x);
                acc[bj].y = fmaxf(acc[bj].y, v.y);
                acc[bj].z = fmaxf(acc[bj].z, v.z);
                acc[bj].w = fmaxf(acc[bj].w, v.w);
            }
        }
    }

    #pragma unroll
    for (int bj = 0; bj < PW; ++bj)
        obase[(size_t)bj * C4] = acc[bj];
}

extern "C" void kernel_launch(void* const* d_in, const int* in_sizes, int n_in,
                              void* d_out, int out_size) {
    const float4* fm   = (const float4*)d_in[0];
    const float4* rois = (const float4*)d_in[1];
    float4*       out  = (float4*)d_out;

    const int n_rois_total = in_sizes[1] / 4;  // 1024

    dim3 grid(n_rois_total, PH);
    roipool_kernel<<<grid, C4>>>(fm, rois, out);
}

// round 6
// speedup vs baseline: 1.1891x; 1.1891x over previous
#include <cuda_runtime.h>
#include <math_constants.h>

// ROI max pooling with smem staging of per-image channel slices.
// feature_map: (16 images, 16, 16, 512) fp32; rois: (1024,4); out: (1024,7,7,512)
//
// Grid: x = channel slice (16 slices of 32 ch), y = image (16), z = roi-group (4 x 16 ROIs)
// Block: 128 threads = 16 ROIs x 8 float4-groups.
// Each block stages its image's 32-channel slice (256 px * 128B = 32KB) into smem,
// then pools 16 ROIs x 49 bins from smem.

#define FM_H 16
#define FM_W 16
#define PH 7
#define PW 7
#define C4_TOTAL 128      // 512 ch / 4
#define SLICE_C4 8        // 32 ch per slice
#define NSLICES 16
#define ROIS_PER_GROUP 16
#define NROIS_PER_IMG 64
#define NPIX (FM_H * FM_W)

__global__ __launch_bounds__(128) void roipool_smem_kernel(
    const float4* __restrict__ fm,     // (16, 256, 128) float4
    const float4* __restrict__ rois,   // (1024) float4
    float4*       __restrict__ out)    // (1024, 49, 128) float4
{
    __shared__ float4 tile[NPIX * SLICE_C4];   // 32 KB

    const int slice = blockIdx.x;     // 0..15
    const int img   = blockIdx.y;     // 0..15
    const int grp   = blockIdx.z;     // 0..3
    const int tid   = threadIdx.x;    // 0..127

    // ---- Stage the channel slice: 256 px * 8 float4 = 2048 float4 ----
    {
        const float4* src = fm + (size_t)img * (NPIX * C4_TOTAL) + slice * SLICE_C4;
        #pragma unroll
        for (int i = 0; i < NPIX * SLICE_C4 / 128; ++i) {   // 16 iters
            int idx = i * 128 + tid;
            int pix = idx >> 3;          // 0..255
            int c   = idx & 7;           // 0..7
            tile[idx] = __ldg(src + (size_t)pix * C4_TOTAL + c);
        }
    }
    __syncthreads();

    // ---- Pool: each thread = one (ROI, float4-group) ----
    const int roi_l = tid >> 3;                 // 0..15
    const int c4s   = tid & 7;                  // 0..7
    const int g     = img * NROIS_PER_IMG + grp * ROIS_PER_GROUP + roi_l;

    const float4 r = __ldg(&rois[g]);
    // Truncation matches jnp .astype(int32) for positive values.
    const int h0 = (int)((float)FM_H * r.x);
    const int w0 = (int)((float)FM_W * r.y);
    const int h1 = (int)((float)FM_H * r.z);
    const int w1 = (int)((float)FM_W * r.w);
    const int hs = (h1 - h0) / PH;
    const int ws = (w1 - w0) / PW;

    // Column windows per bin-col. Reference semantics: bins 0..PW-2 span ws
    // cols; last bin extends to w1. If ws<=0 all in-ROI cols fold into the
    // last bin; other bins stay empty (-inf).
    int cs[PW], ce[PW];
    #pragma unroll
    for (int bj = 0; bj < PW; ++bj) {
        if (ws > 0) {
            cs[bj] = w0 + bj * ws;
            ce[bj] = (bj == PW - 1) ? w1 : cs[bj] + ws;
        } else {
            cs[bj] = (bj == PW - 1) ? w0 : 0;
            ce[bj] = (bj == PW - 1) ? w1 : 0;
        }
    }

    float4* obase = out + (size_t)g * (PH * PW * C4_TOTAL)
                        + slice * SLICE_C4 + c4s;

    for (int bi = 0; bi < PH; ++bi) {
        int rs, re;
        if (hs > 0) {
            rs = h0 + bi * hs;
            re = (bi == PH - 1) ? h1 : rs + hs;
        } else {
            rs = (bi == PH - 1) ? h0 : 0;
            re = (bi == PH - 1) ? h1 : 0;
        }

        float4 acc[PW];
        #pragma unroll
        for (int bj = 0; bj < PW; ++bj)
            acc[bj] = make_float4(-CUDART_INF_F, -CUDART_INF_F,
                                  -CUDART_INF_F, -CUDART_INF_F);

        for (int h = rs; h < re; ++h) {
            const float4* row = tile + (h * FM_W) * SLICE_C4 + c4s;
            #pragma unroll
            for (int bj = 0; bj < PW; ++bj) {
                for (int w = cs[bj]; w < ce[bj]; ++w) {
                    float4 v = row[w * SLICE_C4];
                    acc[bj].x = fmaxf(acc[bj].x, v.x);
                    acc[bj].y = fmaxf(acc[bj].y, v.y);
                    acc[bj].z = fmaxf(acc[bj].z, v.z);
                    acc[bj].w = fmaxf(acc[bj].w, v.w);
                }
            }
        }

        #pragma unroll
        for (int bj = 0; bj < PW; ++bj)
            obase[(size_t)(bi * PW + bj) * C4_TOTAL] = acc[bj];
    }
}

extern "C" void kernel_launch(void* const* d_in, const int* in_sizes, int n_in,
                              void* d_out, int out_size) {
    const float4* fm   = (const float4*)d_in[0];
    const float4* rois = (const float4*)d_in[1];
    float4*       out  = (float4*)d_out;

    dim3 grid(NSLICES, 16, 4);   // slices x images x roi-groups
    roipool_smem_kernel<<<grid, 128>>>(fm, rois, out);
}

// round 7
// speedup vs baseline: 1.3032x; 1.0960x over previous
#include <cuda_runtime.h>
#include <math_constants.h>

// ROI max pooling, two-phase:
//   1) decode_kernel: 1 thread per ROI, packs each of its 49 bin windows into
//      one int: base_pixel(8b) | nrows(5b @ bit 8) | ncols(5b @ bit 16).
//   2) pool_kernel: grid (49 bins, 1024 ROIs), 128 threads (one float4 channel
//      group each). Unpack window, loop nr x nc loads from L2-resident fm,
//      fmax, one coalesced 16B store. Minimal ALU in the hot path.

#define FM_H 16
#define FM_W 16
#define PH 7
#define PW 7
#define C4 128            // 512 channels / 4
#define NROIS 1024
#define NROIS_PER_IMG 64
#define NBINS (PH * PW)

__device__ int g_windows[NROIS * NBINS];

__global__ __launch_bounds__(128) void decode_kernel(
    const float4* __restrict__ rois)
{
    const int g = blockIdx.x * 128 + threadIdx.x;
    if (g >= NROIS) return;

    const float4 r = __ldg(&rois[g]);
    // Truncation matches jnp .astype(int32) for positive values.
    const int h0 = (int)((float)FM_H * r.x);
    const int w0 = (int)((float)FM_W * r.y);
    const int h1 = (int)((float)FM_H * r.z);
    const int w1 = (int)((float)FM_W * r.w);
    const int hs = (h1 - h0) / PH;
    const int ws = (w1 - w0) / PW;

    // Reference semantics per dim: bins 0..P-2 span step rows, last bin
    // extends to the region end. If step<=0, all in-ROI rows fold into the
    // last bin; other bins are empty (-inf output).
    int rs[PH], nr[PH], cs[PW], nc[PW];
    #pragma unroll
    for (int bi = 0; bi < PH; ++bi) {
        if (hs > 0) {
            rs[bi] = h0 + bi * hs;
            nr[bi] = (bi == PH - 1) ? (h1 - rs[bi]) : hs;
        } else {
            rs[bi] = (bi == PH - 1) ? h0 : 0;
            nr[bi] = (bi == PH - 1) ? (h1 - h0) : 0;
        }
    }
    #pragma unroll
    for (int bj = 0; bj < PW; ++bj) {
        if (ws > 0) {
            cs[bj] = w0 + bj * ws;
            nc[bj] = (bj == PW - 1) ? (w1 - cs[bj]) : ws;
        } else {
            cs[bj] = (bj == PW - 1) ? w0 : 0;
            nc[bj] = (bj == PW - 1) ? (w1 - w0) : 0;
        }
    }

    int* wout = g_windows + g * NBINS;
    #pragma unroll
    for (int bi = 0; bi < PH; ++bi) {
        #pragma unroll
        for (int bj = 0; bj < PW; ++bj) {
            int base_px = rs[bi] * FM_W + cs[bj];      // 0..255
            wout[bi * PW + bj] = base_px | (nr[bi] << 8) | (nc[bj] << 16);
        }
    }
}

__global__ __launch_bounds__(C4) void pool_kernel(
    const float4* __restrict__ fm,    // (16 imgs, 256 px, 128 float4)
    float4*       __restrict__ out)   // (1024, 49, 128 float4)
{
    const int bin = blockIdx.x;       // 0..48
    const int g   = blockIdx.y;       // 0..1023
    const int tid = threadIdx.x;      // 0..127

    const int win = __ldg(&g_windows[g * NBINS + bin]);  // uniform -> broadcast
    const int base_px = win & 0xFF;
    const int nr      = (win >> 8) & 0x1F;
    const int nc      = (win >> 16) & 0x1F;

    const float4* p = fm + ((size_t)(g >> 6) * (256 * C4)) + base_px * C4 + tid;

    float4 m = make_float4(-CUDART_INF_F, -CUDART_INF_F,
                           -CUDART_INF_F, -CUDART_INF_F);

    for (int r = 0; r < nr; ++r) {
        const float4* q = p + r * (FM_W * C4);
        for (int c = 0; c < nc; ++c) {
            float4 v = __ldg(q + c * C4);
            m.x = fmaxf(m.x, v.x);
            m.y = fmaxf(m.y, v.y);
            m.z = fmaxf(m.z, v.z);
            m.w = fmaxf(m.w, v.w);
        }
    }

    out[((size_t)g * NBINS + bin) * C4 + tid] = m;
}

extern "C" void kernel_launch(void* const* d_in, const int* in_sizes, int n_in,
                              void* d_out, int out_size) {
    const float4* fm   = (const float4*)d_in[0];
    const float4* rois = (const float4*)d_in[1];
    float4*       out  = (float4*)d_out;

    decode_kernel<<<(NROIS + 127) / 128, 128>>>(rois);

    dim3 grid(NBINS, NROIS);
    pool_kernel<<<grid, C4>>>(fm, out);
}